// round 15
// baseline (speedup 1.0000x reference)
#include <cuda_runtime.h>
#include <cuda_bf16.h>

#define NUM_EMB 1024
#define DIM 256
#define NTOK 65536
#define Q_ELEMS (NTOK * DIM)
#define MT 128                 // tokens per gemm/repair block
#define TPB 64                 // tokens per gather block
#define THRESH 2.0e-4f         // sound candidate margin (>= 2*E, E<=6.6e-5)

// ---- scratch (static device globals; no allocation) ----
__device__ float          g_cnorm[NUM_EMB];
__device__ float          g_xxv[NTOK];
__device__ int            g_idx[NTOK];
__device__ int            g_min[NTOK];
__device__ unsigned int   g_hist[NUM_EMB];
__device__ double         g_sse;
__device__ __nv_bfloat16  g_bhi[NUM_EMB * DIM];
__device__ __nv_bfloat16  g_blo[NUM_EMB * DIM];
__device__ float          g_dap[(size_t)NTOK * NUM_EMB];   // 268 MB approx distances

// m16n8k16 row.col bf16 MMA, fp32 accumulate (acc += A*B)
__device__ __forceinline__ void mma16816(float& d0, float& d1, float& d2, float& d3,
                                         unsigned a0, unsigned a1, unsigned a2, unsigned a3,
                                         unsigned b0, unsigned b1) {
    asm volatile(
        "mma.sync.aligned.m16n8k16.row.col.f32.bf16.bf16.f32 "
        "{%0,%1,%2,%3}, {%4,%5,%6,%7}, {%8,%9}, {%0,%1,%2,%3};"
        : "+f"(d0), "+f"(d1), "+f"(d2), "+f"(d3)
        : "r"(a0), "r"(a1), "r"(a2), "r"(a3), "r"(b0), "r"(b1));
}

// ============================================================
// K0: init — cnorm (exact sequential chain), codebook bf16 split, zeros
// ============================================================
__global__ void k_init(const float* __restrict__ codebook) {
    int i = blockIdx.x * blockDim.x + threadIdx.x;
    if (i < NUM_EMB) {
        const float* row = codebook + i * DIM;
        float s = 0.f;
        for (int d = 0; d < DIM; d++) {
            float c = row[d];
            s = __fadd_rn(s, __fmul_rn(c, c));
            __nv_bfloat16 h = __float2bfloat16(c);
            float r = __fsub_rn(c, __bfloat162float(h));
            g_bhi[i * DIM + d] = h;
            g_blo[i * DIM + d] = __float2bfloat16(r);
        }
        g_cnorm[i] = s;
        g_hist[i] = 0u;
    }
    if (i == 0) g_sse = 0.0;
}

// ============================================================
// K1: 3-GEMM bf16 screen (hh+hl+lh), dapp store + per-token approx min
//   Block: 128 tokens x all 1024 codes, 256 threads (8 warps).
//   Warp w -> token rows [w*16, w*16+16); chunk = 32 codes.
//   Fragments loaded as direct b32 LDS (layouts per PTX m16n8k16 spec).
// ============================================================
__global__ void __launch_bounds__(256, 1)
k_gemm(const float* __restrict__ inputs) {
    extern __shared__ char sm[];
    __nv_bfloat16* xhi = (__nv_bfloat16*)(sm);              // [128][264]
    __nv_bfloat16* xlo = (__nv_bfloat16*)(sm + 67584);      // [128][264]
    __nv_bfloat16* chi = (__nv_bfloat16*)(sm + 135168);     // [32][264]
    __nv_bfloat16* clo = (__nv_bfloat16*)(sm + 152064);     // [32][264]
    float*         sxx = (float*)(sm + 168960);             // [128]
    float*         scc = (float*)(sm + 169472);             // [1024]
    int*          minT = (int*)(sm + 173568);               // [128]

    const int tid  = threadIdx.x;
    const int t0   = blockIdx.x * MT;
    const int batch = t0 >> 10;
    const int hw0   = t0 & 1023;
    const int lane = tid & 31, w = tid >> 5;
    const int g = lane >> 2, tq = lane & 3;

    // ---- split x tile into smem (row-major [tok][d], pad 8 halves) ----
    {
        int tok = tid & 127, dg = tid >> 7;
        const float* base = inputs + (size_t)batch * DIM * 1024 + hw0 + tok;
        for (int d = dg; d < DIM; d += 2) {
            float x = base[(size_t)d * 1024];
            __nv_bfloat16 h = __float2bfloat16(x);
            float r = __fsub_rn(x, __bfloat162float(h));
            xhi[tok * 264 + d] = h;
            xlo[tok * 264 + d] = __float2bfloat16(r);
        }
    }
    for (int i = tid; i < NUM_EMB; i += 256) scc[i] = g_cnorm[i];
    if (tid < MT) minT[tid] = 0x7FFFFFFF;
    // ---- exact xx chain per token (sequential scalar, matches ref) ----
    if (tid < MT) {
        const float* base = inputs + (size_t)batch * DIM * 1024 + hw0 + tid;
        float s = 0.f;
        for (int d = 0; d < DIM; d++) {
            float v = base[(size_t)d * 1024];
            s = __fadd_rn(s, __fmul_rn(v, v));
        }
        sxx[tid] = s;
        g_xxv[t0 + tid] = s;
    }
    __syncthreads();

    const unsigned* xhi32 = (const unsigned*)xhi;
    const unsigned* xlo32 = (const unsigned*)xlo;
    const unsigned* chi32 = (const unsigned*)chi;
    const unsigned* clo32 = (const unsigned*)clo;
    const int arow = (w * 16 + g) * 132;   // b32 row base for this lane's A rows

    for (int cb = 0; cb < NUM_EMB; cb += 32) {
        __syncthreads();
        {   // load 32-code chunk hi+lo (uint4, row stride 33 uint4 = 132 b32)
            uint4* dh = (uint4*)chi; uint4* dl = (uint4*)clo;
            const uint4* shc = (const uint4*)g_bhi;
            const uint4* slc = (const uint4*)g_blo;
            for (int i = tid; i < 32 * 32; i += 256) {
                int j = i >> 5, dq = i & 31;
                dh[j * 33 + dq] = shc[(size_t)(cb + j) * 32 + dq];
                dl[j * 33 + dq] = slc[(size_t)(cb + j) * 32 + dq];
            }
        }
        __syncthreads();

        float acc[4][4];
        #pragma unroll
        for (int nt = 0; nt < 4; nt++)
            acc[nt][0] = acc[nt][1] = acc[nt][2] = acc[nt][3] = 0.f;

        #pragma unroll 4
        for (int ks = 0; ks < 16; ks++) {
            int ao = arow + ks * 8 + tq;
            unsigned ah0 = xhi32[ao],           ah1 = xhi32[ao + 8 * 132];
            unsigned ah2 = xhi32[ao + 4],       ah3 = xhi32[ao + 8 * 132 + 4];
            unsigned al0 = xlo32[ao],           al1 = xlo32[ao + 8 * 132];
            unsigned al2 = xlo32[ao + 4],       al3 = xlo32[ao + 8 * 132 + 4];
            #pragma unroll
            for (int nt = 0; nt < 4; nt++) {
                int bo = (nt * 8 + g) * 132 + ks * 8 + tq;
                unsigned bh0 = chi32[bo], bh1 = chi32[bo + 4];
                unsigned bl0 = clo32[bo], bl1 = clo32[bo + 4];
                mma16816(acc[nt][0], acc[nt][1], acc[nt][2], acc[nt][3],
                         ah0, ah1, ah2, ah3, bh0, bh1);   // hi*hi
                mma16816(acc[nt][0], acc[nt][1], acc[nt][2], acc[nt][3],
                         ah0, ah1, ah2, ah3, bl0, bl1);   // hi*lo
                mma16816(acc[nt][0], acc[nt][1], acc[nt][2], acc[nt][3],
                         al0, al1, al2, al3, bh0, bh1);   // lo*hi
            }
        }

        // ---- screen: dapp = fl(fl(xx+cc) - 2*dotapp); store + running min ----
        int r0 = w * 16 + g, r1 = r0 + 8;
        float xx0 = sxx[r0], xx1 = sxx[r1];
        float m0 = 3.4e38f, m1 = 3.4e38f;
        #pragma unroll
        for (int nt = 0; nt < 4; nt++) {
            int c0 = cb + nt * 8 + 2 * tq;
            float cc0 = scc[c0], cc1 = scc[c0 + 1];
            float d00 = __fmaf_rn(-2.f, acc[nt][0], __fadd_rn(xx0, cc0));
            float d01 = __fmaf_rn(-2.f, acc[nt][1], __fadd_rn(xx0, cc1));
            float d10 = __fmaf_rn(-2.f, acc[nt][2], __fadd_rn(xx1, cc0));
            float d11 = __fmaf_rn(-2.f, acc[nt][3], __fadd_rn(xx1, cc1));
            *(float2*)&g_dap[(size_t)(t0 + r0) * NUM_EMB + c0] = make_float2(d00, d01);
            *(float2*)&g_dap[(size_t)(t0 + r1) * NUM_EMB + c0] = make_float2(d10, d11);
            m0 = fminf(m0, fminf(d00, d01));
            m1 = fminf(m1, fminf(d10, d11));
        }
        atomicMin(&minT[r0], __float_as_int(m0));   // positive floats: int order == float order
        atomicMin(&minT[r1], __float_as_int(m1));
    }
    __syncthreads();
    if (tid < MT) g_min[t0 + tid] = minT[tid];
}

// ============================================================
// K2: repair — exact fp32-chain recompute of screened candidates,
//     (distance, index)-lexicographic min == reference argmin.
// ============================================================
__global__ void __launch_bounds__(256, 1)
k_repair(const float* __restrict__ inputs, const float* __restrict__ codebook,
         float* __restrict__ out_idx) {
    extern __shared__ float xbuf[];      // [128][257] fp32 x tile
    __shared__ int lists[8][32];
    const int tid = threadIdx.x, lane = tid & 31, w = tid >> 5;
    const int t0 = blockIdx.x * MT;
    const int batch = t0 >> 10, hw0 = t0 & 1023;

    {   // stage fp32 x tile (coalesced over tokens)
        int tok = tid & 127, dg = tid >> 7;
        const float* base = inputs + (size_t)batch * DIM * 1024 + hw0 + tok;
        for (int d = dg; d < DIM; d += 2)
            xbuf[tok * 257 + d] = base[(size_t)d * 1024];
    }
    __syncthreads();

    for (int i = 0; i < 16; i++) {
        int tl = w * 16 + i;
        int tok = t0 + tl;
        float fmin = __int_as_float(g_min[tok]);
        float th = fmin + THRESH;
        const float* drow = g_dap + (size_t)tok * NUM_EMB;

        int cnt = 0; bool ovf = false;
        for (int rep = 0; rep < 32; rep++) {
            float v = drow[rep * 32 + lane];
            bool p = (v <= th);
            unsigned m = __ballot_sync(0xFFFFFFFFu, p);
            int pc = __popc(m);
            if (cnt + pc > 32) { ovf = true; break; }   // uniform branch
            if (p) lists[w][cnt + __popc(m & ((1u << lane) - 1u))] = rep * 32 + lane;
            cnt += pc;
        }
        __syncwarp();

        const float* xb = xbuf + tl * 257;
        float xx = g_xxv[tok];
        unsigned long long key = ~0ull;
        if (!ovf) {
            int c = (lane < cnt) ? lists[w][lane] : -1;
            const float* cp = codebook + (size_t)(c < 0 ? 0 : c) * DIM;
            float s = 0.f;
            #pragma unroll 8
            for (int d = 0; d < DIM; d++) s = __fmaf_rn(xb[d], cp[d], s);  // exact ref chain
            if (c >= 0) {
                float de = __fmaf_rn(-2.f, s, __fadd_rn(xx, g_cnorm[c]));
                key = ((unsigned long long)__float_as_uint(de) << 32) | (unsigned)c;
            }
        } else {
            for (int r = 0; r < 32; r++) {   // rare fallback: exact scan of all codes
                int c = r * 32 + lane;
                const float* cp = codebook + (size_t)c * DIM;
                float s = 0.f;
                #pragma unroll 8
                for (int d = 0; d < DIM; d++) s = __fmaf_rn(xb[d], cp[d], s);
                float de = __fmaf_rn(-2.f, s, __fadd_rn(xx, g_cnorm[c]));
                unsigned long long k2 =
                    ((unsigned long long)__float_as_uint(de) << 32) | (unsigned)c;
                key = (k2 < key) ? k2 : key;
            }
        }
        #pragma unroll
        for (int off = 16; off; off >>= 1) {
            unsigned long long o = __shfl_xor_sync(0xFFFFFFFFu, key, off);
            key = (o < key) ? o : key;
        }
        if (lane == 0) {
            int best = (int)(key & 0xFFFFFFFFull);
            g_idx[tok] = best;
            out_idx[tok] = (float)best;
        }
    }
}

// ============================================================
// K3: gather quantized rows, STE write (x + (q - x)), MSE + histogram
// ============================================================
__global__ void __launch_bounds__(256)
k_gather(const float* __restrict__ inputs,
         const float* __restrict__ codebook,
         float* __restrict__ out_q) {
    const int tid   = threadIdx.x;
    const int t0    = blockIdx.x * TPB;
    const int batch = t0 >> 10;
    const int hw0   = t0 & 1023;
    const int tok   = tid & 63;
    const int dg    = tid >> 6;

    const int t   = t0 + tok;
    const int row = g_idx[t];
    const float* crow  = codebook + (size_t)row * DIM;
    const float* xbase = inputs + (size_t)batch * DIM * 1024 + hw0 + tok;
    float*       obase = out_q  + (size_t)batch * DIM * 1024 + hw0 + tok;

    float sse = 0.f;
    #pragma unroll 4
    for (int d = dg; d < DIM; d += 4) {
        float q = crow[d];
        float x = xbase[(size_t)d * 1024];
        float diff = __fsub_rn(q, x);
        sse = __fmaf_rn(diff, diff, sse);
        obase[(size_t)d * 1024] = __fadd_rn(x, diff);   // x + (q - x)
    }
    #pragma unroll
    for (int o = 16; o; o >>= 1) sse += __shfl_down_sync(0xFFFFFFFFu, sse, o);
    __shared__ float warpsum[8];
    if ((tid & 31) == 0) warpsum[tid >> 5] = sse;
    __syncthreads();
    if (tid == 0) {
        float s = 0.f;
        #pragma unroll
        for (int i = 0; i < 8; i++) s += warpsum[i];
        atomicAdd(&g_sse, (double)s);
    }
    if (dg == 0) atomicAdd(&g_hist[row], 1u);
}

// ============================================================
// K4: perplexity + loss
// ============================================================
__global__ void k_final(float* __restrict__ out) {
    const int i = threadIdx.x;  // 1024 threads
    float p = (float)g_hist[i] * (1.0f / (float)NTOK);
    float term = p * logf(p + 1e-10f);
    #pragma unroll
    for (int o = 16; o; o >>= 1) term += __shfl_down_sync(0xFFFFFFFFu, term, o);
    __shared__ float ws[32];
    if ((i & 31) == 0) ws[i >> 5] = term;
    __syncthreads();
    if (i < 32) {
        float v = ws[i];
        #pragma unroll
        for (int o = 16; o; o >>= 1) v += __shfl_down_sync(0xFFFFFFFFu, v, o);
        if (i == 0) {
            out[0] = (float)(1.25 * g_sse / (double)Q_ELEMS);
            out[1 + (size_t)Q_ELEMS] = expf(-v);
        }
    }
}

// ============================================================
// launch
// ============================================================
extern "C" void kernel_launch(void* const* d_in, const int* in_sizes, int n_in,
                              void* d_out, int out_size) {
    const float* inputs   = (const float*)d_in[0];   // [64,256,32,32] f32
    const float* codebook = (const float*)d_in[1];   // [1024,256] f32
    float* out = (float*)d_out;
    float* out_q   = out + 1;
    float* out_idx = out + 2 + (size_t)Q_ELEMS;

    (void)in_sizes; (void)n_in; (void)out_size;

    static const int SMEM_GEMM = 174080;
    static const int SMEM_REP  = 128 * 257 * (int)sizeof(float);   // 131584
    cudaFuncSetAttribute(k_gemm,   cudaFuncAttributeMaxDynamicSharedMemorySize, SMEM_GEMM);
    cudaFuncSetAttribute(k_repair, cudaFuncAttributeMaxDynamicSharedMemorySize, SMEM_REP);

    k_init<<<4, 256>>>(codebook);
    k_gemm<<<NTOK / MT, 256, SMEM_GEMM>>>(inputs);
    k_repair<<<NTOK / MT, 256, SMEM_REP>>>(inputs, codebook, out_idx);
    k_gather<<<NTOK / TPB, 256>>>(inputs, codebook, out_q);
    k_final<<<1, 1024>>>(out);
}